// round 11
// baseline (speedup 1.0000x reference)
#include <cuda_runtime.h>
#include <cuda_bf16.h>

// Additive (Bahdanau) self-attention. B=4, L=1024, D=64, U=32.
// e[i,j] = sum_u tanh(qb[i,u] + k[j,u]) * Wa[u];  a = softmax_j(e);  out = a @ inputs.
// - ba cancels in softmax (dropped); |e| <= ||Wa||_1 ~ 2.6 -> no max-subtraction needed.
// - Wa pre-scaled by log2(e) so p = ex2(e').
// - j-split: each CTA handles 64 rows x half the j-range; partial (v, l) merged
//   by a tiny combine kernel (softmax partials add since no max shift is used).

#define B_ 4
#define L_ 1024
#define D_ 64
#define U_ 32
#define HL_ 512          // j-half length
#define NROWS 4096       // B_*L_

// Scratch (allocation-free rule: device globals)
__device__ float g_qb[B_ * L_ * U_];       // [b][l][u]  (qb = inputs@Wt + bh)
__device__ float g_kswz[B_ * L_ * U_];     // [b][j][u]  XOR-swizzled 16B chunks
__device__ float g_vpart[2 * NROWS * D_];  // [half][row][d] unnormalized partial v
__device__ float g_lpart[2 * NROWS];       // [half][row] partial denominators

__device__ __forceinline__ float tanh_fast(float x) {
    float r; asm("tanh.approx.f32 %0, %1;" : "=f"(r) : "f"(x)); return r;
}
__device__ __forceinline__ float ex2_fast(float x) {
    float r; asm("ex2.approx.f32 %0, %1;" : "=f"(r) : "f"(x)); return r;
}
__device__ __forceinline__ unsigned long long dup2(float s) {
    unsigned long long r; asm("mov.b64 %0, {%1, %1};" : "=l"(r) : "f"(s)); return r;
}
__device__ __forceinline__ void fma2(unsigned long long& a, unsigned long long b,
                                     unsigned long long c) {
    asm("fma.rn.f32x2 %0, %1, %2, %0;" : "+l"(a) : "l"(b), "l"(c));
}

// ---------------------------------------------------------------------------
// Pass 1: qb = inputs@Wt + bh ; kswz = swizzled (inputs@Wx)
// ---------------------------------------------------------------------------
__global__ __launch_bounds__(256) void precompute_kernel(
    const float* __restrict__ inputs,
    const float* __restrict__ Wt,
    const float* __restrict__ Wx,
    const float* __restrict__ bh)
{
    __shared__ float in_s[8 * D_];
    __shared__ float wt_s[D_ * U_];
    __shared__ float wx_s[D_ * U_];

    const int tid = threadIdx.x;
    const int base_row = blockIdx.x * 8;

    for (int i = tid; i < 8 * D_; i += 256) in_s[i] = inputs[base_row * D_ + i];
    for (int i = tid; i < D_ * U_; i += 256) { wt_s[i] = Wt[i]; wx_s[i] = Wx[i]; }
    __syncthreads();

    const int r = tid >> 5;
    const int u = tid & 31;
    const int row = base_row + r;

    float aq = bh[u];
    float ak = 0.f;
#pragma unroll
    for (int d = 0; d < D_; d++) {
        const float iv = in_s[r * D_ + d];
        aq = fmaf(iv, wt_s[d * U_ + u], aq);
        ak = fmaf(iv, wx_s[d * U_ + u], ak);
    }
    g_qb[row * U_ + u] = aq;

    const int li = row & (L_ - 1);
    const int g = u >> 2;
    const int c = g ^ (li & 7);          // 16B-chunk XOR swizzle keyed by j&7
    g_kswz[(size_t)row * U_ + c * 4 + (u & 3)] = ak;
}

// ---------------------------------------------------------------------------
// Pass 2: fused e -> exp -> partial a@V over one j-half.
// 512 threads = 16 warps; warp w owns rows {w, w+16, w+32, w+48} of a 64-row slab.
// grid = 64 slabs x 2 halves = 128 CTAs. smem: k-half 64KB + q 8KB + pb 16KB.
// ---------------------------------------------------------------------------
__global__ __launch_bounds__(512, 1) void attn_kernel(
    const float* __restrict__ inputs,
    const float* __restrict__ Wa)
{
    extern __shared__ float sm[];
    float*  k_s = sm;                               // HL_*U_ = 16384 floats
    float*  q_s = sm + HL_ * U_;                    // 64*U_  = 2048 floats
    float4* p_s = (float4*)(sm + HL_ * U_ + 64 * U_);  // [2][16][32] float4

    const int slab = blockIdx.x >> 1;
    const int h    = blockIdx.x & 1;
    const int b    = slab >> 4;                     // 16 slabs per batch
    const int row_base = slab * 64;

    {   // stage k-half (flat copy, pre-swizzled) + q slab
        const float4* src = (const float4*)(g_kswz + ((size_t)b * L_ + h * HL_) * U_);
        float4* dst = (float4*)k_s;
#pragma unroll
        for (int i = threadIdx.x; i < (HL_ * U_) / 4; i += 512) dst[i] = src[i];
        const float4* qsrc = (const float4*)(g_qb + (size_t)row_base * U_);
        float4* qdst = (float4*)q_s;
        for (int i = threadIdx.x; i < (64 * U_) / 4; i += 512) qdst[i] = qsrc[i];
    }

    const float LOG2E = 1.4426950408889634f;
    float wa[U_];
#pragma unroll
    for (int u = 0; u < U_; u++) wa[u] = Wa[u] * LOG2E;

    __syncthreads();

    const int warp = threadIdx.x >> 5;
    const int lane = threadIdx.x & 31;

    const float4* qp0 = (const float4*)(q_s + (warp +  0) * U_);
    const float4* qp1 = (const float4*)(q_s + (warp + 16) * U_);
    const float4* qp2 = (const float4*)(q_s + (warp + 32) * U_);
    const float4* qp3 = (const float4*)(q_s + (warp + 48) * U_);

    const unsigned long long* __restrict__ V8 =
        (const unsigned long long*)(inputs + (size_t)b * L_ * D_) + (size_t)h * HL_ * (D_ / 2);

    unsigned long long v0 = 0ull, v1 = 0ull, v2 = 0ull, v3 = 0ull;
    float l0 = 0.f, l1 = 0.f, l2 = 0.f, l3 = 0.f;

#pragma unroll 2
    for (int jt = 0; jt < HL_ / 32; jt++) {
        const int j = jt * 32 + lane;
        const float4* krow = (const float4*)(k_s + (size_t)j * U_);
        const int sw = lane & 7;

        // --- Phase A: e for 4 rows at column j (lane = j) ---
        float a0 = 0, b0 = 0, a1 = 0, b1 = 0, a2 = 0, b2 = 0, a3 = 0, b3 = 0;
#pragma unroll
        for (int g = 0; g < 8; g++) {
            const float4 kk = krow[g ^ sw];     // conflict-free via swizzle
            const float4 qa = qp0[g];
            const float4 qb = qp1[g];
            const float4 qc = qp2[g];
            const float4 qd = qp3[g];
            const float w0 = wa[g * 4 + 0], w1 = wa[g * 4 + 1];
            const float w2 = wa[g * 4 + 2], w3 = wa[g * 4 + 3];
            a0 = fmaf(tanh_fast(qa.x + kk.x), w0, a0);
            b0 = fmaf(tanh_fast(qa.y + kk.y), w1, b0);
            a0 = fmaf(tanh_fast(qa.z + kk.z), w2, a0);
            b0 = fmaf(tanh_fast(qa.w + kk.w), w3, b0);
            a1 = fmaf(tanh_fast(qb.x + kk.x), w0, a1);
            b1 = fmaf(tanh_fast(qb.y + kk.y), w1, b1);
            a1 = fmaf(tanh_fast(qb.z + kk.z), w2, a1);
            b1 = fmaf(tanh_fast(qb.w + kk.w), w3, b1);
            a2 = fmaf(tanh_fast(qc.x + kk.x), w0, a2);
            b2 = fmaf(tanh_fast(qc.y + kk.y), w1, b2);
            a2 = fmaf(tanh_fast(qc.z + kk.z), w2, a2);
            b2 = fmaf(tanh_fast(qc.w + kk.w), w3, b2);
            a3 = fmaf(tanh_fast(qd.x + kk.x), w0, a3);
            b3 = fmaf(tanh_fast(qd.y + kk.y), w1, b3);
            a3 = fmaf(tanh_fast(qd.z + kk.z), w2, a3);
            b3 = fmaf(tanh_fast(qd.w + kk.w), w3, b3);
        }
        const float p0 = ex2_fast(a0 + b0);
        const float p1 = ex2_fast(a1 + b1);
        const float p2 = ex2_fast(a2 + b2);
        const float p3 = ex2_fast(a3 + b3);
        l0 += p0; l1 += p1; l2 += p2; l3 += p3;

        float4* pb = p_s + (size_t)(jt & 1) * 16 * 32 + warp * 32;
        pb[lane] = make_float4(p0, p1, p2, p3);
        __syncwarp();

        // --- Phase B: v[r] += p[r][j2] * V[j2,:]; lane owns d = {2*lane, 2*lane+1} ---
        const unsigned long long* __restrict__ Vt =
            V8 + (size_t)jt * 32 * (D_ / 2) + lane;
#pragma unroll
        for (int j2 = 0; j2 < 32; j2++) {
            const float4 pp = pb[j2];                      // LDS.128 broadcast
            const unsigned long long vv = Vt[(size_t)j2 * (D_ / 2)];
            fma2(v0, dup2(pp.x), vv);
            fma2(v1, dup2(pp.y), vv);
            fma2(v2, dup2(pp.z), vv);
            fma2(v3, dup2(pp.w), vv);
        }
    }

    // warp-sum denominators
#pragma unroll
    for (int off = 16; off; off >>= 1) {
        l0 += __shfl_xor_sync(0xffffffffu, l0, off);
        l1 += __shfl_xor_sync(0xffffffffu, l1, off);
        l2 += __shfl_xor_sync(0xffffffffu, l2, off);
        l3 += __shfl_xor_sync(0xffffffffu, l3, off);
    }

    // store partials
    float2* vp = (float2*)g_vpart + (size_t)h * NROWS * (D_ / 2);
    const int r0 = row_base + warp;
    float2 t;
    asm("mov.b64 {%0, %1}, %2;" : "=f"(t.x), "=f"(t.y) : "l"(v0));
    vp[(size_t)(r0 +  0) * (D_ / 2) + lane] = t;
    asm("mov.b64 {%0, %1}, %2;" : "=f"(t.x), "=f"(t.y) : "l"(v1));
    vp[(size_t)(r0 + 16) * (D_ / 2) + lane] = t;
    asm("mov.b64 {%0, %1}, %2;" : "=f"(t.x), "=f"(t.y) : "l"(v2));
    vp[(size_t)(r0 + 32) * (D_ / 2) + lane] = t;
    asm("mov.b64 {%0, %1}, %2;" : "=f"(t.x), "=f"(t.y) : "l"(v3));
    vp[(size_t)(r0 + 48) * (D_ / 2) + lane] = t;

    if (lane == 0) {
        float* lp = g_lpart + (size_t)h * NROWS;
        lp[r0 +  0] = l0;
        lp[r0 + 16] = l1;
        lp[r0 + 32] = l2;
        lp[r0 + 48] = l3;
    }
}

// ---------------------------------------------------------------------------
// Pass 3: out = (vA + vB) / (lA + lB + 1e-8)
// ---------------------------------------------------------------------------
__global__ __launch_bounds__(512) void combine_kernel(float* __restrict__ out)
{
    const int idx  = blockIdx.x * 512 + threadIdx.x;    // 0 .. NROWS*32-1
    const int row  = idx >> 5;
    const int lane = idx & 31;

    const float l = g_lpart[row] + g_lpart[NROWS + row] + 1e-8f;
    const float inv = 1.f / l;

    const float2* vp = (const float2*)g_vpart;
    const float2 aa = vp[(size_t)row * (D_ / 2) + lane];
    const float2 bb = vp[(size_t)(NROWS + row) * (D_ / 2) + lane];

    float2 o;
    o.x = (aa.x + bb.x) * inv;
    o.y = (aa.y + bb.y) * inv;
    ((float2*)out)[(size_t)row * (D_ / 2) + lane] = o;
}

// ---------------------------------------------------------------------------
extern "C" void kernel_launch(void* const* d_in, const int* in_sizes, int n_in,
                              void* d_out, int out_size)
{
    const float* inputs = (const float*)d_in[0];
    const float* Wt     = (const float*)d_in[1];
    const float* Wx     = (const float*)d_in[2];
    const float* Wa     = (const float*)d_in[3];
    const float* bh     = (const float*)d_in[4];
    float* out = (float*)d_out;

    precompute_kernel<<<(B_ * L_) / 8, 256>>>(inputs, Wt, Wx, bh);

    const int smem = (HL_ * U_ + 64 * U_ + 2 * 16 * 32 * 4) * (int)sizeof(float); // 90112
    cudaFuncSetAttribute(attn_kernel, cudaFuncAttributeMaxDynamicSharedMemorySize, smem);
    attn_kernel<<<128, 512, smem>>>(inputs, Wa);

    combine_kernel<<<(NROWS * 32) / 512, 512>>>(out);
}

// round 12
// speedup vs baseline: 1.0046x; 1.0046x over previous
#include <cuda_runtime.h>
#include <cuda_bf16.h>

// Additive (Bahdanau) self-attention. B=4, L=1024, D=64, U=32.
// e[i,j] = sum_u tanh(qb[i,u] + k[j,u]) * Wa[u];  a = softmax_j(e);  out = a @ inputs.
// - ba cancels in softmax (dropped); |e| <= ||Wa||_1 ~ 2.6 -> no max-subtraction needed.
// - Wa pre-scaled by log2(e) so p = ex2(e').
// - j-split: each CTA handles 64 rows x half the j-range; partial (v, l) merged
//   by a tiny combine kernel (softmax partials add since no max shift is used).

#define B_ 4
#define L_ 1024
#define D_ 64
#define U_ 32
#define HL_ 512          // j-half length
#define NROWS 4096       // B_*L_

// Scratch (allocation-free rule: device globals)
__device__ float g_qb[B_ * L_ * U_];       // [b][l][u]  (qb = inputs@Wt + bh)
__device__ float g_kswz[B_ * L_ * U_];     // [b][j][u]  XOR-swizzled 16B chunks
__device__ float g_vpart[2 * NROWS * D_];  // [half][row][d] unnormalized partial v
__device__ float g_lpart[2 * NROWS];       // [half][row] partial denominators

__device__ __forceinline__ float tanh_fast(float x) {
    float r; asm("tanh.approx.f32 %0, %1;" : "=f"(r) : "f"(x)); return r;
}
__device__ __forceinline__ float ex2_fast(float x) {
    float r; asm("ex2.approx.f32 %0, %1;" : "=f"(r) : "f"(x)); return r;
}
__device__ __forceinline__ unsigned long long dup2(float s) {
    unsigned long long r; asm("mov.b64 %0, {%1, %1};" : "=l"(r) : "f"(s)); return r;
}
__device__ __forceinline__ void fma2(unsigned long long& a, unsigned long long b,
                                     unsigned long long c) {
    asm("fma.rn.f32x2 %0, %1, %2, %0;" : "+l"(a) : "l"(b), "l"(c));
}

// ---------------------------------------------------------------------------
// Pass 1: qb = inputs@Wt + bh ; kswz = swizzled (inputs@Wx)
// ---------------------------------------------------------------------------
__global__ __launch_bounds__(256) void precompute_kernel(
    const float* __restrict__ inputs,
    const float* __restrict__ Wt,
    const float* __restrict__ Wx,
    const float* __restrict__ bh)
{
    __shared__ float in_s[8 * D_];
    __shared__ float wt_s[D_ * U_];
    __shared__ float wx_s[D_ * U_];

    const int tid = threadIdx.x;
    const int base_row = blockIdx.x * 8;

    for (int i = tid; i < 8 * D_; i += 256) in_s[i] = inputs[base_row * D_ + i];
    for (int i = tid; i < D_ * U_; i += 256) { wt_s[i] = Wt[i]; wx_s[i] = Wx[i]; }
    __syncthreads();

    const int r = tid >> 5;
    const int u = tid & 31;
    const int row = base_row + r;

    float aq = bh[u];
    float ak = 0.f;
#pragma unroll
    for (int d = 0; d < D_; d++) {
        const float iv = in_s[r * D_ + d];
        aq = fmaf(iv, wt_s[d * U_ + u], aq);
        ak = fmaf(iv, wx_s[d * U_ + u], ak);
    }
    g_qb[row * U_ + u] = aq;

    const int li = row & (L_ - 1);
    const int g = u >> 2;
    const int c = g ^ (li & 7);          // 16B-chunk XOR swizzle keyed by j&7
    g_kswz[(size_t)row * U_ + c * 4 + (u & 3)] = ak;
}

// ---------------------------------------------------------------------------
// Pass 2: fused e -> exp -> partial a@V over one j-half.
// 512 threads = 16 warps; warp w owns rows {w, w+16, w+32, w+48} of a 64-row slab.
// grid = 64 slabs x 2 halves = 128 CTAs. smem: k-half 64KB + q 8KB + pb 16KB.
// ---------------------------------------------------------------------------
__global__ __launch_bounds__(512, 1) void attn_kernel(
    const float* __restrict__ inputs,
    const float* __restrict__ Wa)
{
    extern __shared__ float sm[];
    float*  k_s = sm;                               // HL_*U_ = 16384 floats
    float*  q_s = sm + HL_ * U_;                    // 64*U_  = 2048 floats
    float4* p_s = (float4*)(sm + HL_ * U_ + 64 * U_);  // [2][16][32] float4

    const int slab = blockIdx.x >> 1;
    const int h    = blockIdx.x & 1;
    const int b    = slab >> 4;                     // 16 slabs per batch
    const int row_base = slab * 64;

    {   // stage k-half (flat copy, pre-swizzled) + q slab
        const float4* src = (const float4*)(g_kswz + ((size_t)b * L_ + h * HL_) * U_);
        float4* dst = (float4*)k_s;
#pragma unroll
        for (int i = threadIdx.x; i < (HL_ * U_) / 4; i += 512) dst[i] = src[i];
        const float4* qsrc = (const float4*)(g_qb + (size_t)row_base * U_);
        float4* qdst = (float4*)q_s;
        for (int i = threadIdx.x; i < (64 * U_) / 4; i += 512) qdst[i] = qsrc[i];
    }

    const float LOG2E = 1.4426950408889634f;
    float wa[U_];
#pragma unroll
    for (int u = 0; u < U_; u++) wa[u] = Wa[u] * LOG2E;

    __syncthreads();

    const int warp = threadIdx.x >> 5;
    const int lane = threadIdx.x & 31;

    const float4* qp0 = (const float4*)(q_s + (warp +  0) * U_);
    const float4* qp1 = (const float4*)(q_s + (warp + 16) * U_);
    const float4* qp2 = (const float4*)(q_s + (warp + 32) * U_);
    const float4* qp3 = (const float4*)(q_s + (warp + 48) * U_);

    const unsigned long long* __restrict__ V8 =
        (const unsigned long long*)(inputs + (size_t)b * L_ * D_) + (size_t)h * HL_ * (D_ / 2);

    unsigned long long v0 = 0ull, v1 = 0ull, v2 = 0ull, v3 = 0ull;
    float l0 = 0.f, l1 = 0.f, l2 = 0.f, l3 = 0.f;

#pragma unroll 2
    for (int jt = 0; jt < HL_ / 32; jt++) {
        const int j = jt * 32 + lane;
        const float4* krow = (const float4*)(k_s + (size_t)j * U_);
        const int sw = lane & 7;

        // --- Phase A: e for 4 rows at column j (lane = j) ---
        float a0 = 0, b0 = 0, a1 = 0, b1 = 0, a2 = 0, b2 = 0, a3 = 0, b3 = 0;
#pragma unroll
        for (int g = 0; g < 8; g++) {
            const float4 kk = krow[g ^ sw];     // conflict-free via swizzle
            const float4 qa = qp0[g];
            const float4 qb = qp1[g];
            const float4 qc = qp2[g];
            const float4 qd = qp3[g];
            const float w0 = wa[g * 4 + 0], w1 = wa[g * 4 + 1];
            const float w2 = wa[g * 4 + 2], w3 = wa[g * 4 + 3];
            a0 = fmaf(tanh_fast(qa.x + kk.x), w0, a0);
            b0 = fmaf(tanh_fast(qa.y + kk.y), w1, b0);
            a0 = fmaf(tanh_fast(qa.z + kk.z), w2, a0);
            b0 = fmaf(tanh_fast(qa.w + kk.w), w3, b0);
            a1 = fmaf(tanh_fast(qb.x + kk.x), w0, a1);
            b1 = fmaf(tanh_fast(qb.y + kk.y), w1, b1);
            a1 = fmaf(tanh_fast(qb.z + kk.z), w2, a1);
            b1 = fmaf(tanh_fast(qb.w + kk.w), w3, b1);
            a2 = fmaf(tanh_fast(qc.x + kk.x), w0, a2);
            b2 = fmaf(tanh_fast(qc.y + kk.y), w1, b2);
            a2 = fmaf(tanh_fast(qc.z + kk.z), w2, a2);
            b2 = fmaf(tanh_fast(qc.w + kk.w), w3, b2);
            a3 = fmaf(tanh_fast(qd.x + kk.x), w0, a3);
            b3 = fmaf(tanh_fast(qd.y + kk.y), w1, b3);
            a3 = fmaf(tanh_fast(qd.z + kk.z), w2, a3);
            b3 = fmaf(tanh_fast(qd.w + kk.w), w3, b3);
        }
        const float p0 = ex2_fast(a0 + b0);
        const float p1 = ex2_fast(a1 + b1);
        const float p2 = ex2_fast(a2 + b2);
        const float p3 = ex2_fast(a3 + b3);
        l0 += p0; l1 += p1; l2 += p2; l3 += p3;

        float4* pb = p_s + (size_t)(jt & 1) * 16 * 32 + warp * 32;
        pb[lane] = make_float4(p0, p1, p2, p3);
        __syncwarp();

        // --- Phase B: v[r] += p[r][j2] * V[j2,:]; lane owns d = {2*lane, 2*lane+1} ---
        const unsigned long long* __restrict__ Vt =
            V8 + (size_t)jt * 32 * (D_ / 2) + lane;
#pragma unroll
        for (int j2 = 0; j2 < 32; j2++) {
            const float4 pp = pb[j2];                      // LDS.128 broadcast
            const unsigned long long vv = Vt[(size_t)j2 * (D_ / 2)];
            fma2(v0, dup2(pp.x), vv);
            fma2(v1, dup2(pp.y), vv);
            fma2(v2, dup2(pp.z), vv);
            fma2(v3, dup2(pp.w), vv);
        }
    }

    // warp-sum denominators
#pragma unroll
    for (int off = 16; off; off >>= 1) {
        l0 += __shfl_xor_sync(0xffffffffu, l0, off);
        l1 += __shfl_xor_sync(0xffffffffu, l1, off);
        l2 += __shfl_xor_sync(0xffffffffu, l2, off);
        l3 += __shfl_xor_sync(0xffffffffu, l3, off);
    }

    // store partials
    float2* vp = (float2*)g_vpart + (size_t)h * NROWS * (D_ / 2);
    const int r0 = row_base + warp;
    float2 t;
    asm("mov.b64 {%0, %1}, %2;" : "=f"(t.x), "=f"(t.y) : "l"(v0));
    vp[(size_t)(r0 +  0) * (D_ / 2) + lane] = t;
    asm("mov.b64 {%0, %1}, %2;" : "=f"(t.x), "=f"(t.y) : "l"(v1));
    vp[(size_t)(r0 + 16) * (D_ / 2) + lane] = t;
    asm("mov.b64 {%0, %1}, %2;" : "=f"(t.x), "=f"(t.y) : "l"(v2));
    vp[(size_t)(r0 + 32) * (D_ / 2) + lane] = t;
    asm("mov.b64 {%0, %1}, %2;" : "=f"(t.x), "=f"(t.y) : "l"(v3));
    vp[(size_t)(r0 + 48) * (D_ / 2) + lane] = t;

    if (lane == 0) {
        float* lp = g_lpart + (size_t)h * NROWS;
        lp[r0 +  0] = l0;
        lp[r0 + 16] = l1;
        lp[r0 + 32] = l2;
        lp[r0 + 48] = l3;
    }
}

// ---------------------------------------------------------------------------
// Pass 3: out = (vA + vB) / (lA + lB + 1e-8)
// ---------------------------------------------------------------------------
__global__ __launch_bounds__(512) void combine_kernel(float* __restrict__ out)
{
    const int idx  = blockIdx.x * 512 + threadIdx.x;    // 0 .. NROWS*32-1
    const int row  = idx >> 5;
    const int lane = idx & 31;

    const float l = g_lpart[row] + g_lpart[NROWS + row] + 1e-8f;
    const float inv = 1.f / l;

    const float2* vp = (const float2*)g_vpart;
    const float2 aa = vp[(size_t)row * (D_ / 2) + lane];
    const float2 bb = vp[(size_t)(NROWS + row) * (D_ / 2) + lane];

    float2 o;
    o.x = (aa.x + bb.x) * inv;
    o.y = (aa.y + bb.y) * inv;
    ((float2*)out)[(size_t)row * (D_ / 2) + lane] = o;
}

// ---------------------------------------------------------------------------
extern "C" void kernel_launch(void* const* d_in, const int* in_sizes, int n_in,
                              void* d_out, int out_size)
{
    const float* inputs = (const float*)d_in[0];
    const float* Wt     = (const float*)d_in[1];
    const float* Wx     = (const float*)d_in[2];
    const float* Wa     = (const float*)d_in[3];
    const float* bh     = (const float*)d_in[4];
    float* out = (float*)d_out;

    precompute_kernel<<<(B_ * L_) / 8, 256>>>(inputs, Wt, Wx, bh);

    const int smem = (HL_ * U_ + 64 * U_ + 2 * 16 * 32 * 4) * (int)sizeof(float); // 90112
    cudaFuncSetAttribute(attn_kernel, cudaFuncAttributeMaxDynamicSharedMemorySize, smem);
    attn_kernel<<<128, 512, smem>>>(inputs, Wa);

    combine_kernel<<<(NROWS * 32) / 512, 512>>>(out);
}

// round 14
// speedup vs baseline: 1.0052x; 1.0006x over previous
#include <cuda_runtime.h>
#include <cuda_bf16.h>

// Additive (Bahdanau) self-attention. B=4, L=1024, D=64, U=32.
// e[i,j] = sum_u tanh(qb[i,u] + k[j,u]) * Wa[u];  a = softmax_j(e);  out = a @ inputs.
// - ba cancels in softmax (dropped); |e| <= ||Wa||_1 ~ 2.6 -> no max-subtraction needed.
// - Wa pre-scaled by log2(e) so p = ex2(e').
// - j-split: each CTA handles 64 rows x half the j-range; partial (v, l) merged
//   by a tiny combine kernel (softmax partials add since no max shift is used).

#define B_ 4
#define L_ 1024
#define D_ 64
#define U_ 32
#define HL_ 512          // j-half length
#define NROWS 4096       // B_*L_

// Scratch (allocation-free rule: device globals)
__device__ float g_qb[B_ * L_ * U_];       // [b][l][u]  (qb = inputs@Wt + bh)
__device__ float g_kswz[B_ * L_ * U_];     // [b][j][u]  XOR-swizzled 16B chunks
__device__ float g_vpart[2 * NROWS * D_];  // [half][row][d] unnormalized partial v
__device__ float g_lpart[2 * NROWS];       // [half][row] partial denominators

__device__ __forceinline__ float tanh_fast(float x) {
    float r; asm("tanh.approx.f32 %0, %1;" : "=f"(r) : "f"(x)); return r;
}
__device__ __forceinline__ float ex2_fast(float x) {
    float r; asm("ex2.approx.f32 %0, %1;" : "=f"(r) : "f"(x)); return r;
}
__device__ __forceinline__ unsigned long long dup2(float s) {
    unsigned long long r; asm("mov.b64 %0, {%1, %1};" : "=l"(r) : "f"(s)); return r;
}
__device__ __forceinline__ void fma2(unsigned long long& a, unsigned long long b,
                                     unsigned long long c) {
    asm("fma.rn.f32x2 %0, %1, %2, %0;" : "+l"(a) : "l"(b), "l"(c));
}

// ---------------------------------------------------------------------------
// Pass 1: qb = inputs@Wt + bh ; kswz = swizzled (inputs@Wx)
// ---------------------------------------------------------------------------
__global__ __launch_bounds__(256) void precompute_kernel(
    const float* __restrict__ inputs,
    const float* __restrict__ Wt,
    const float* __restrict__ Wx,
    const float* __restrict__ bh)
{
    __shared__ float in_s[8 * D_];
    __shared__ float wt_s[D_ * U_];
    __shared__ float wx_s[D_ * U_];

    const int tid = threadIdx.x;
    const int base_row = blockIdx.x * 8;

    for (int i = tid; i < 8 * D_; i += 256) in_s[i] = inputs[base_row * D_ + i];
    for (int i = tid; i < D_ * U_; i += 256) { wt_s[i] = Wt[i]; wx_s[i] = Wx[i]; }
    __syncthreads();

    const int r = tid >> 5;
    const int u = tid & 31;
    const int row = base_row + r;

    float aq = bh[u];
    float ak = 0.f;
#pragma unroll
    for (int d = 0; d < D_; d++) {
        const float iv = in_s[r * D_ + d];
        aq = fmaf(iv, wt_s[d * U_ + u], aq);
        ak = fmaf(iv, wx_s[d * U_ + u], ak);
    }
    g_qb[row * U_ + u] = aq;

    const int li = row & (L_ - 1);
    const int g = u >> 2;
    const int c = g ^ (li & 7);          // 16B-chunk XOR swizzle keyed by j&7
    g_kswz[(size_t)row * U_ + c * 4 + (u & 3)] = ak;
}

// ---------------------------------------------------------------------------
// Pass 2: fused e -> exp -> partial a@V over one j-half.
// 512 threads = 16 warps; warp w owns rows {w, w+16, w+32, w+48} of a 64-row slab.
// grid = 64 slabs x 2 halves = 128 CTAs. smem: k-half 64KB + q 8KB + pb 16KB.
// ---------------------------------------------------------------------------
__global__ __launch_bounds__(512, 1) void attn_kernel(
    const float* __restrict__ inputs,
    const float* __restrict__ Wa)
{
    extern __shared__ float sm[];
    float*  k_s = sm;                               // HL_*U_ = 16384 floats
    float*  q_s = sm + HL_ * U_;                    // 64*U_  = 2048 floats
    float4* p_s = (float4*)(sm + HL_ * U_ + 64 * U_);  // [2][16][32] float4

    const int slab = blockIdx.x >> 1;
    const int h    = blockIdx.x & 1;
    const int b    = slab >> 4;                     // 16 slabs per batch
    const int row_base = slab * 64;

    {   // stage k-half (flat copy, pre-swizzled) + q slab
        const float4* src = (const float4*)(g_kswz + ((size_t)b * L_ + h * HL_) * U_);
        float4* dst = (float4*)k_s;
#pragma unroll
        for (int i = threadIdx.x; i < (HL_ * U_) / 4; i += 512) dst[i] = src[i];
        const float4* qsrc = (const float4*)(g_qb + (size_t)row_base * U_);
        float4* qdst = (float4*)q_s;
        for (int i = threadIdx.x; i < (64 * U_) / 4; i += 512) qdst[i] = qsrc[i];
    }

    const float LOG2E = 1.4426950408889634f;
    float wa[U_];
#pragma unroll
    for (int u = 0; u < U_; u++) wa[u] = Wa[u] * LOG2E;

    __syncthreads();

    const int warp = threadIdx.x >> 5;
    const int lane = threadIdx.x & 31;

    const float4* qp0 = (const float4*)(q_s + (warp +  0) * U_);
    const float4* qp1 = (const float4*)(q_s + (warp + 16) * U_);
    const float4* qp2 = (const float4*)(q_s + (warp + 32) * U_);
    const float4* qp3 = (const float4*)(q_s + (warp + 48) * U_);

    const unsigned long long* __restrict__ V8 =
        (const unsigned long long*)(inputs + (size_t)b * L_ * D_) + (size_t)h * HL_ * (D_ / 2);

    unsigned long long v0 = 0ull, v1 = 0ull, v2 = 0ull, v3 = 0ull;
    float l0 = 0.f, l1 = 0.f, l2 = 0.f, l3 = 0.f;

#pragma unroll 2
    for (int jt = 0; jt < HL_ / 32; jt++) {
        const int j = jt * 32 + lane;
        const float4* krow = (const float4*)(k_s + (size_t)j * U_);
        const int sw = lane & 7;

        // --- Phase A: e for 4 rows at column j (lane = j) ---
        float a0 = 0, b0 = 0, a1 = 0, b1 = 0, a2 = 0, b2 = 0, a3 = 0, b3 = 0;
#pragma unroll
        for (int g = 0; g < 8; g++) {
            const float4 kk = krow[g ^ sw];     // conflict-free via swizzle
            const float4 qa = qp0[g];
            const float4 qb = qp1[g];
            const float4 qc = qp2[g];
            const float4 qd = qp3[g];
            const float w0 = wa[g * 4 + 0], w1 = wa[g * 4 + 1];
            const float w2 = wa[g * 4 + 2], w3 = wa[g * 4 + 3];
            a0 = fmaf(tanh_fast(qa.x + kk.x), w0, a0);
            b0 = fmaf(tanh_fast(qa.y + kk.y), w1, b0);
            a0 = fmaf(tanh_fast(qa.z + kk.z), w2, a0);
            b0 = fmaf(tanh_fast(qa.w + kk.w), w3, b0);
            a1 = fmaf(tanh_fast(qb.x + kk.x), w0, a1);
            b1 = fmaf(tanh_fast(qb.y + kk.y), w1, b1);
            a1 = fmaf(tanh_fast(qb.z + kk.z), w2, a1);
            b1 = fmaf(tanh_fast(qb.w + kk.w), w3, b1);
            a2 = fmaf(tanh_fast(qc.x + kk.x), w0, a2);
            b2 = fmaf(tanh_fast(qc.y + kk.y), w1, b2);
            a2 = fmaf(tanh_fast(qc.z + kk.z), w2, a2);
            b2 = fmaf(tanh_fast(qc.w + kk.w), w3, b2);
            a3 = fmaf(tanh_fast(qd.x + kk.x), w0, a3);
            b3 = fmaf(tanh_fast(qd.y + kk.y), w1, b3);
            a3 = fmaf(tanh_fast(qd.z + kk.z), w2, a3);
            b3 = fmaf(tanh_fast(qd.w + kk.w), w3, b3);
        }
        const float p0 = ex2_fast(a0 + b0);
        const float p1 = ex2_fast(a1 + b1);
        const float p2 = ex2_fast(a2 + b2);
        const float p3 = ex2_fast(a3 + b3);
        l0 += p0; l1 += p1; l2 += p2; l3 += p3;

        float4* pb = p_s + (size_t)(jt & 1) * 16 * 32 + warp * 32;
        pb[lane] = make_float4(p0, p1, p2, p3);
        __syncwarp();

        // --- Phase B: v[r] += p[r][j2] * V[j2,:]; lane owns d = {2*lane, 2*lane+1} ---
        const unsigned long long* __restrict__ Vt =
            V8 + (size_t)jt * 32 * (D_ / 2) + lane;
#pragma unroll
        for (int j2 = 0; j2 < 32; j2++) {
            const float4 pp = pb[j2];                      // LDS.128 broadcast
            const unsigned long long vv = Vt[(size_t)j2 * (D_ / 2)];
            fma2(v0, dup2(pp.x), vv);
            fma2(v1, dup2(pp.y), vv);
            fma2(v2, dup2(pp.z), vv);
            fma2(v3, dup2(pp.w), vv);
        }
    }

    // warp-sum denominators
#pragma unroll
    for (int off = 16; off; off >>= 1) {
        l0 += __shfl_xor_sync(0xffffffffu, l0, off);
        l1 += __shfl_xor_sync(0xffffffffu, l1, off);
        l2 += __shfl_xor_sync(0xffffffffu, l2, off);
        l3 += __shfl_xor_sync(0xffffffffu, l3, off);
    }

    // store partials
    float2* vp = (float2*)g_vpart + (size_t)h * NROWS * (D_ / 2);
    const int r0 = row_base + warp;
    float2 t;
    asm("mov.b64 {%0, %1}, %2;" : "=f"(t.x), "=f"(t.y) : "l"(v0));
    vp[(size_t)(r0 +  0) * (D_ / 2) + lane] = t;
    asm("mov.b64 {%0, %1}, %2;" : "=f"(t.x), "=f"(t.y) : "l"(v1));
    vp[(size_t)(r0 + 16) * (D_ / 2) + lane] = t;
    asm("mov.b64 {%0, %1}, %2;" : "=f"(t.x), "=f"(t.y) : "l"(v2));
    vp[(size_t)(r0 + 32) * (D_ / 2) + lane] = t;
    asm("mov.b64 {%0, %1}, %2;" : "=f"(t.x), "=f"(t.y) : "l"(v3));
    vp[(size_t)(r0 + 48) * (D_ / 2) + lane] = t;

    if (lane == 0) {
        float* lp = g_lpart + (size_t)h * NROWS;
        lp[r0 +  0] = l0;
        lp[r0 + 16] = l1;
        lp[r0 + 32] = l2;
        lp[r0 + 48] = l3;
    }
}

// ---------------------------------------------------------------------------
// Pass 3: out = (vA + vB) / (lA + lB + 1e-8)
// ---------------------------------------------------------------------------
__global__ __launch_bounds__(512) void combine_kernel(float* __restrict__ out)
{
    const int idx  = blockIdx.x * 512 + threadIdx.x;    // 0 .. NROWS*32-1
    const int row  = idx >> 5;
    const int lane = idx & 31;

    const float l = g_lpart[row] + g_lpart[NROWS + row] + 1e-8f;
    const float inv = 1.f / l;

    const float2* vp = (const float2*)g_vpart;
    const float2 aa = vp[(size_t)row * (D_ / 2) + lane];
    const float2 bb = vp[(size_t)(NROWS + row) * (D_ / 2) + lane];

    float2 o;
    o.x = (aa.x + bb.x) * inv;
    o.y = (aa.y + bb.y) * inv;
    ((float2*)out)[(size_t)row * (D_ / 2) + lane] = o;
}

// ---------------------------------------------------------------------------
extern "C" void kernel_launch(void* const* d_in, const int* in_sizes, int n_in,
                              void* d_out, int out_size)
{
    const float* inputs = (const float*)d_in[0];
    const float* Wt     = (const float*)d_in[1];
    const float* Wx     = (const float*)d_in[2];
    const float* Wa     = (const float*)d_in[3];
    const float* bh     = (const float*)d_in[4];
    float* out = (float*)d_out;

    precompute_kernel<<<(B_ * L_) / 8, 256>>>(inputs, Wt, Wx, bh);

    const int smem = (HL_ * U_ + 64 * U_ + 2 * 16 * 32 * 4) * (int)sizeof(float); // 90112
    cudaFuncSetAttribute(attn_kernel, cudaFuncAttributeMaxDynamicSharedMemorySize, smem);
    attn_kernel<<<128, 512, smem>>>(inputs, Wa);

    combine_kernel<<<(NROWS * 32) / 512, 512>>>(out);
}